// round 1
// baseline (speedup 1.0000x reference)
#include <cuda_runtime.h>
#include <cuda_bf16.h>
#include <math.h>
#include <stdint.h>

// ---------------- problem constants ----------------
#define BB 4
#define TT 1024
#define DD 1024
#define HH 16
#define HD 64
#define LL 8
#define VV 4096
#define BT (BB*TT)       // 4096
#define D4 (4*DD)        // 4096

// ---------------- scratch (no alloc allowed) ----------------
__device__ float g_x[BT*DD];
__device__ float g_h[BT*DD];
__device__ float g_q[BT*DD];
__device__ float g_k[BT*DD];
__device__ float g_v[BT*DD];
__device__ float g_y[BT*DD];
__device__ float g_mid[(size_t)BT*D4];

// ---------------- helpers ----------------
__device__ __forceinline__ float warpSum(float v) {
    #pragma unroll
    for (int o = 16; o > 0; o >>= 1) v += __shfl_xor_sync(0xffffffffu, v, o);
    return v;
}
__device__ __forceinline__ float warpMax(float v) {
    #pragma unroll
    for (int o = 16; o > 0; o >>= 1) v = fmaxf(v, __shfl_xor_sync(0xffffffffu, v, o));
    return v;
}

// ---------------- embedding ----------------
__global__ void embed_kernel(const int* __restrict__ idx,
                             const float* __restrict__ tok,
                             const float* __restrict__ pos,
                             float* __restrict__ x) {
    int row = blockIdx.x;              // b*T + t
    int t   = row & (TT - 1);
    int token = idx[row];
    const float4* tr = reinterpret_cast<const float4*>(tok + (size_t)token * DD);
    const float4* pr = reinterpret_cast<const float4*>(pos + (size_t)t * DD);
    float4* xr = reinterpret_cast<float4*>(x + (size_t)row * DD);
    int i = threadIdx.x;               // 256 threads, D/4 = 256 float4s
    float4 a = tr[i], p = pr[i];
    float4 o; o.x = a.x + p.x; o.y = a.y + p.y; o.z = a.z + p.z; o.w = a.w + p.w;
    xr[i] = o;
}

// ---------------- layernorm (one row per block, 256 threads) ----------------
__global__ void ln_kernel(const float* __restrict__ in, float* __restrict__ out,
                          const float* __restrict__ w, const float* __restrict__ b) {
    __shared__ float red[8];
    __shared__ float s_mean, s_rstd;
    int row = blockIdx.x;
    int tid = threadIdx.x;
    int lane = tid & 31, wid = tid >> 5;

    const float4* r = reinterpret_cast<const float4*>(in + (size_t)row * DD);
    float4 v = r[tid];

    float s = v.x + v.y + v.z + v.w;
    s = warpSum(s);
    if (lane == 0) red[wid] = s;
    __syncthreads();
    if (wid == 0) {
        float t = (lane < 8) ? red[lane] : 0.f;
        t = warpSum(t);
        if (lane == 0) s_mean = t * (1.0f / DD);
    }
    __syncthreads();
    float mean = s_mean;
    float dx = v.x - mean, dy = v.y - mean, dz = v.z - mean, dw = v.w - mean;
    float sq = dx*dx + dy*dy + dz*dz + dw*dw;
    sq = warpSum(sq);
    __syncthreads();
    if (lane == 0) red[wid] = sq;
    __syncthreads();
    if (wid == 0) {
        float t = (lane < 8) ? red[lane] : 0.f;
        t = warpSum(t);
        if (lane == 0) s_rstd = rsqrtf(t * (1.0f / DD) + 1e-5f);
    }
    __syncthreads();
    float rstd = s_rstd;

    const float4* wr = reinterpret_cast<const float4*>(w);
    const float4* br = reinterpret_cast<const float4*>(b);
    float4 ww = wr[tid], bb = br[tid];
    float4 o;
    o.x = dx * rstd * ww.x + bb.x;
    o.y = dy * rstd * ww.y + bb.y;
    o.z = dz * rstd * ww.z + bb.z;
    o.w = dw * rstd * ww.w + bb.w;
    reinterpret_cast<float4*>(out + (size_t)row * DD)[tid] = o;
}

// ---------------- SGEMM: C[M,N] = A[M,K] * W[N,K]^T (+bias)(+res)(gelu) ----
// 128x128 tile, BK=8, 256 threads, 8x8 per thread (split 4+4).
template <int GELU, int RES>
__global__ void __launch_bounds__(256, 2)
gemm_kernel(const float* __restrict__ A, const float* __restrict__ W,
            const float* __restrict__ bias, const float* __restrict__ res,
            float* __restrict__ C, int M, int N, int K) {
    __shared__ float As[8][132];
    __shared__ float Bs[8][132];

    int bm = blockIdx.y * 128;
    int bn = blockIdx.x * 128;
    int t  = threadIdx.x;
    int arow = t >> 1;
    int acol = (t & 1) * 4;
    int tx = t & 15;       // col group
    int ty = t >> 4;       // row group

    float acc[8][8];
    #pragma unroll
    for (int i = 0; i < 8; i++)
        #pragma unroll
        for (int j = 0; j < 8; j++) acc[i][j] = 0.f;

    const int ksteps = K >> 3;
    for (int kt = 0; kt < ksteps; kt++) {
        int kc = (kt << 3) + acol;
        float4 av = *reinterpret_cast<const float4*>(&A[(size_t)(bm + arow) * K + kc]);
        float4 bv = *reinterpret_cast<const float4*>(&W[(size_t)(bn + arow) * K + kc]);
        As[acol + 0][arow] = av.x; As[acol + 1][arow] = av.y;
        As[acol + 2][arow] = av.z; As[acol + 3][arow] = av.w;
        Bs[acol + 0][arow] = bv.x; Bs[acol + 1][arow] = bv.y;
        Bs[acol + 2][arow] = bv.z; Bs[acol + 3][arow] = bv.w;
        __syncthreads();

        #pragma unroll
        for (int kk = 0; kk < 8; kk++) {
            float4 a0 = *reinterpret_cast<const float4*>(&As[kk][ty * 4]);
            float4 a1 = *reinterpret_cast<const float4*>(&As[kk][64 + ty * 4]);
            float4 b0 = *reinterpret_cast<const float4*>(&Bs[kk][tx * 4]);
            float4 b1 = *reinterpret_cast<const float4*>(&Bs[kk][64 + tx * 4]);
            float ra[8] = {a0.x, a0.y, a0.z, a0.w, a1.x, a1.y, a1.z, a1.w};
            float rb[8] = {b0.x, b0.y, b0.z, b0.w, b1.x, b1.y, b1.z, b1.w};
            #pragma unroll
            for (int i = 0; i < 8; i++)
                #pragma unroll
                for (int j = 0; j < 8; j++)
                    acc[i][j] = fmaf(ra[i], rb[j], acc[i][j]);
        }
        __syncthreads();
    }

    #pragma unroll
    for (int i = 0; i < 8; i++) {
        int r = bm + ((i < 4) ? (ty * 4 + i) : (64 + ty * 4 + i - 4));
        #pragma unroll
        for (int j = 0; j < 8; j++) {
            int c = bn + ((j < 4) ? (tx * 4 + j) : (64 + tx * 4 + j - 4));
            float val = acc[i][j];
            if (bias) val += bias[c];
            if (RES)  val += res[(size_t)r * N + c];
            if (GELU) val = 0.5f * val * (1.0f + erff(val * 0.70710678118654752f));
            C[(size_t)r * N + c] = val;
        }
    }
}

// ---------------- causal attention: one block per (b,h,qt) ----------------
// 128 threads. scores in smem, streaming softmax not needed (full row fits).
__global__ void attn_kernel(const float* __restrict__ Q, const float* __restrict__ Kp,
                            const float* __restrict__ Vp, float* __restrict__ Y) {
    __shared__ float qs[HD];
    __shared__ float sc[TT];
    __shared__ float red[4];
    __shared__ float s_mx, s_inv;
    __shared__ float part[128];

    int qt = blockIdx.x;
    int h  = blockIdx.y;
    int b  = blockIdx.z;
    int tid = threadIdx.x;
    int lane = tid & 31, wid = tid >> 5;
    int nk = qt + 1;

    size_t qoff = ((size_t)(b * TT + qt) * DD) + h * HD;
    if (tid < HD) qs[tid] = Q[qoff + tid];
    __syncthreads();

    // scores
    const float4* qs4 = reinterpret_cast<const float4*>(qs);
    for (int kk = tid; kk < nk; kk += 128) {
        const float4* kr = reinterpret_cast<const float4*>(Kp + ((size_t)(b * TT + kk) * DD) + h * HD);
        float s = 0.f;
        #pragma unroll
        for (int i = 0; i < HD / 4; i++) {
            float4 kv = kr[i];
            float4 qv = qs4[i];
            s += qv.x * kv.x + qv.y * kv.y + qv.z * kv.z + qv.w * kv.w;
        }
        sc[kk] = s * 0.125f;  // 1/sqrt(64)
    }
    __syncthreads();

    // max
    float lm = -1e30f;
    for (int kk = tid; kk < nk; kk += 128) lm = fmaxf(lm, sc[kk]);
    lm = warpMax(lm);
    if (lane == 0) red[wid] = lm;
    __syncthreads();
    if (tid == 0) {
        float m = red[0];
        for (int i = 1; i < 4; i++) m = fmaxf(m, red[i]);
        s_mx = m;
    }
    __syncthreads();
    float mx = s_mx;

    // exp + sum
    float ls = 0.f;
    for (int kk = tid; kk < nk; kk += 128) {
        float p = __expf(sc[kk] - mx);
        sc[kk] = p;
        ls += p;
    }
    ls = warpSum(ls);
    __syncthreads();
    if (lane == 0) red[wid] = ls;
    __syncthreads();
    if (tid == 0) s_inv = 1.0f / (red[0] + red[1] + red[2] + red[3]);
    __syncthreads();
    float inv = s_inv;

    // y = P * V  (threads 0..63 d, two halves over k)
    int d = tid & 63;
    int half = tid >> 6;
    float acc = 0.f;
    for (int kk = half; kk < nk; kk += 2)
        acc += sc[kk] * Vp[((size_t)(b * TT + kk) * DD) + h * HD + d];
    part[tid] = acc;
    __syncthreads();
    if (tid < HD)
        Y[qoff + tid] = (part[tid] + part[tid + 64]) * inv;
}

// ---------------- launch ----------------
extern "C" void kernel_launch(void* const* d_in, const int* in_sizes, int n_in,
                              void* d_out, int out_size) {
    const int*   idx    = (const int*)  d_in[0];
    const float* tok    = (const float*)d_in[1];
    const float* pos    = (const float*)d_in[2];
    const float* ln1_w  = (const float*)d_in[3];
    const float* ln1_b  = (const float*)d_in[4];
    const float* Wq     = (const float*)d_in[5];
    const float* bq     = (const float*)d_in[6];
    const float* Wk     = (const float*)d_in[7];
    const float* bk     = (const float*)d_in[8];
    const float* Wv     = (const float*)d_in[9];
    const float* bv     = (const float*)d_in[10];
    const float* Wproj  = (const float*)d_in[11];
    const float* bproj  = (const float*)d_in[12];
    const float* ln2_w  = (const float*)d_in[13];
    const float* ln2_b  = (const float*)d_in[14];
    const float* W1     = (const float*)d_in[15];
    const float* b1     = (const float*)d_in[16];
    const float* W2     = (const float*)d_in[17];
    const float* b2     = (const float*)d_in[18];
    const float* lnf_w  = (const float*)d_in[19];
    const float* lnf_b  = (const float*)d_in[20];
    const float* Wlogit = (const float*)d_in[21];
    const float* Wdev   = (const float*)d_in[22];
    float* out = (float*)d_out;

    float *x, *h, *q, *k, *v, *y, *mid;
    cudaGetSymbolAddress((void**)&x,   g_x);
    cudaGetSymbolAddress((void**)&h,   g_h);
    cudaGetSymbolAddress((void**)&q,   g_q);
    cudaGetSymbolAddress((void**)&k,   g_k);
    cudaGetSymbolAddress((void**)&v,   g_v);
    cudaGetSymbolAddress((void**)&y,   g_y);
    cudaGetSymbolAddress((void**)&mid, g_mid);

    embed_kernel<<<BT, 256>>>(idx, tok, pos, x);

    dim3 gD(DD / 128, BT / 128);    // N=1024
    dim3 g4(D4 / 128, BT / 128);    // N=4096
    dim3 gV(VV / 128, BT / 128);    // N=4096 heads
    dim3 ga(TT, HH, BB);

    for (int l = 0; l < LL; l++) {
        const float* wq = Wq + (size_t)l * DD * DD;
        const float* wk = Wk + (size_t)l * DD * DD;
        const float* wv = Wv + (size_t)l * DD * DD;
        const float* wp = Wproj + (size_t)l * DD * DD;
        const float* w1 = W1 + (size_t)l * D4 * DD;
        const float* w2 = W2 + (size_t)l * DD * D4;

        ln_kernel<<<BT, 256>>>(x, h, ln1_w + l * DD, ln1_b + l * DD);

        gemm_kernel<0, 0><<<gD, 256>>>(h, wq, bq + l * DD, nullptr, q, BT, DD, DD);
        gemm_kernel<0, 0><<<gD, 256>>>(h, wk, bk + l * DD, nullptr, k, BT, DD, DD);
        gemm_kernel<0, 0><<<gD, 256>>>(h, wv, bv + l * DD, nullptr, v, BT, DD, DD);

        attn_kernel<<<ga, 128>>>(q, k, v, y);

        gemm_kernel<0, 1><<<gD, 256>>>(y, wp, bproj + l * DD, x, x, BT, DD, DD);

        ln_kernel<<<BT, 256>>>(x, h, ln2_w + l * DD, ln2_b + l * DD);

        gemm_kernel<1, 0><<<g4, 256>>>(h, w1, b1 + (size_t)l * D4, nullptr, mid, BT, D4, DD);
        gemm_kernel<0, 1><<<gD, 256>>>(mid, w2, b2 + l * DD, x, x, BT, DD, D4);
    }

    ln_kernel<<<BT, 256>>>(x, h, lnf_w, lnf_b);

    gemm_kernel<0, 0><<<gV, 256>>>(h, Wlogit, nullptr, nullptr, out, BT, VV, DD);
    gemm_kernel<0, 0><<<gV, 256>>>(h, Wdev, nullptr, nullptr, out + (size_t)BT * VV, BT, VV, DD);
}

// round 2
// speedup vs baseline: 2.7694x; 2.7694x over previous
#include <cuda_runtime.h>
#include <cuda_bf16.h>
#include <math.h>
#include <stdint.h>

// ---------------- problem constants ----------------
#define BB 4
#define TT 1024
#define DD 1024
#define HH 16
#define HD 64
#define LL 8
#define VV 4096
#define BT (BB*TT)       // 4096
#define D4 (4*DD)        // 4096

// ---------------- scratch (no alloc allowed) ----------------
__device__ float g_x[BT*DD];
__device__ float g_h[BT*DD];
__device__ float g_q[BT*DD];
__device__ float g_k[BT*DD];
__device__ float g_v[BT*DD];
__device__ float g_y[BT*DD];
__device__ float g_mid[(size_t)BT*D4];

// ---------------- helpers ----------------
__device__ __forceinline__ float warpSum(float v) {
    #pragma unroll
    for (int o = 16; o > 0; o >>= 1) v += __shfl_xor_sync(0xffffffffu, v, o);
    return v;
}

__device__ __forceinline__ uint32_t pack2bf(float a, float b) {
    __nv_bfloat162 h = __floats2bfloat162_rn(a, b);
    return *reinterpret_cast<uint32_t*>(&h);
}

__device__ __forceinline__ void split2(float f, float& hi, float& lo) {
    hi = __bfloat162float(__float2bfloat16_rn(f));
    lo = f - hi;
}

#define MMA_BF16(c, a, b) \
  asm volatile("mma.sync.aligned.m16n8k16.row.col.f32.bf16.bf16.f32 " \
    "{%0,%1,%2,%3}, {%4,%5,%6,%7}, {%8,%9}, {%0,%1,%2,%3};" \
    : "+f"((c)[0]), "+f"((c)[1]), "+f"((c)[2]), "+f"((c)[3]) \
    : "r"((a)[0]), "r"((a)[1]), "r"((a)[2]), "r"((a)[3]), "r"((b)[0]), "r"((b)[1]))

// ---------------- embedding ----------------
__global__ void embed_kernel(const int* __restrict__ idx,
                             const float* __restrict__ tok,
                             const float* __restrict__ pos,
                             float* __restrict__ x) {
    int row = blockIdx.x;
    int t   = row & (TT - 1);
    int token = idx[row];
    const float4* tr = reinterpret_cast<const float4*>(tok + (size_t)token * DD);
    const float4* pr = reinterpret_cast<const float4*>(pos + (size_t)t * DD);
    float4* xr = reinterpret_cast<float4*>(x + (size_t)row * DD);
    int i = threadIdx.x;
    float4 a = tr[i], p = pr[i];
    float4 o; o.x = a.x + p.x; o.y = a.y + p.y; o.z = a.z + p.z; o.w = a.w + p.w;
    xr[i] = o;
}

// ---------------- layernorm ----------------
__global__ void ln_kernel(const float* __restrict__ in, float* __restrict__ out,
                          const float* __restrict__ w, const float* __restrict__ b) {
    __shared__ float red[8];
    __shared__ float s_mean, s_rstd;
    int row = blockIdx.x;
    int tid = threadIdx.x;
    int lane = tid & 31, wid = tid >> 5;

    const float4* r = reinterpret_cast<const float4*>(in + (size_t)row * DD);
    float4 v = r[tid];

    float s = v.x + v.y + v.z + v.w;
    s = warpSum(s);
    if (lane == 0) red[wid] = s;
    __syncthreads();
    if (wid == 0) {
        float t = (lane < 8) ? red[lane] : 0.f;
        t = warpSum(t);
        if (lane == 0) s_mean = t * (1.0f / DD);
    }
    __syncthreads();
    float mean = s_mean;
    float dx = v.x - mean, dy = v.y - mean, dz = v.z - mean, dw = v.w - mean;
    float sq = dx*dx + dy*dy + dz*dz + dw*dw;
    sq = warpSum(sq);
    __syncthreads();
    if (lane == 0) red[wid] = sq;
    __syncthreads();
    if (wid == 0) {
        float t = (lane < 8) ? red[lane] : 0.f;
        t = warpSum(t);
        if (lane == 0) s_rstd = rsqrtf(t * (1.0f / DD) + 1e-5f);
    }
    __syncthreads();
    float rstd = s_rstd;

    const float4* wr = reinterpret_cast<const float4*>(w);
    const float4* br = reinterpret_cast<const float4*>(b);
    float4 ww = wr[tid], bb = br[tid];
    float4 o;
    o.x = dx * rstd * ww.x + bb.x;
    o.y = dy * rstd * ww.y + bb.y;
    o.z = dz * rstd * ww.z + bb.z;
    o.w = dw * rstd * ww.w + bb.w;
    reinterpret_cast<float4*>(out + (size_t)row * DD)[tid] = o;
}

// ---------------- bf16-split tensor-core GEMM ----------------
// C[M,N] = A[M,K] * W[N,K]^T (+bias)(+res)(gelu)
// 128x128 tile, BK=32, 256 threads (8 warps, 4x2), warp tile 32x64.
// a = a_hi + a_lo (bf16 each); C ~= Ahi*Whi + Ahi*Wlo + Alo*Whi (fp32 acc).
template <int GELU, int RES>
__global__ void __launch_bounds__(256, 1)
mma_gemm(const float* __restrict__ A, const float* __restrict__ W,
         const float* __restrict__ bias, const float* __restrict__ res,
         float* __restrict__ C, int M, int N, int K) {
    __shared__ uint32_t sAh[128][20];
    __shared__ uint32_t sAl[128][20];
    __shared__ uint32_t sBh[128][20];
    __shared__ uint32_t sBl[128][20];

    const int t = threadIdx.x;
    const int lane = t & 31, wid = t >> 5;
    const int wm = (wid & 3) * 32;
    const int wn = (wid >> 2) * 64;
    const int gid = lane >> 2, tig = lane & 3;
    const int bm = blockIdx.y * 128;
    const int bn = blockIdx.x * 128;

    float acc[2][8][4];
    #pragma unroll
    for (int mt = 0; mt < 2; mt++)
        #pragma unroll
        for (int nt = 0; nt < 8; nt++)
            #pragma unroll
            for (int i = 0; i < 4; i++) acc[mt][nt][i] = 0.f;

    float4 stA[4], stB[4];
    const int row_l = t >> 3;        // 0..31 per 256/8
    const int c4_l  = t & 7;

    const int ktot = K >> 5;

    // prologue load
    #pragma unroll
    for (int i = 0; i < 4; i++) {
        int row = row_l + i * 32;
        stA[i] = *reinterpret_cast<const float4*>(&A[(size_t)(bm + row) * K + c4_l * 4]);
        stB[i] = *reinterpret_cast<const float4*>(&W[(size_t)(bn + row) * K + c4_l * 4]);
    }

    for (int kt = 0; kt < ktot; kt++) {
        __syncthreads();
        // convert + store staged tile
        #pragma unroll
        for (int i = 0; i < 4; i++) {
            int row = row_l + i * 32;
            float hx, lx, hy, ly, hz, lz, hw, lw;
            split2(stA[i].x, hx, lx); split2(stA[i].y, hy, ly);
            split2(stA[i].z, hz, lz); split2(stA[i].w, hw, lw);
            sAh[row][c4_l * 2]     = pack2bf(hx, hy);
            sAh[row][c4_l * 2 + 1] = pack2bf(hz, hw);
            sAl[row][c4_l * 2]     = pack2bf(lx, ly);
            sAl[row][c4_l * 2 + 1] = pack2bf(lz, lw);
            split2(stB[i].x, hx, lx); split2(stB[i].y, hy, ly);
            split2(stB[i].z, hz, lz); split2(stB[i].w, hw, lw);
            sBh[row][c4_l * 2]     = pack2bf(hx, hy);
            sBh[row][c4_l * 2 + 1] = pack2bf(hz, hw);
            sBl[row][c4_l * 2]     = pack2bf(lx, ly);
            sBl[row][c4_l * 2 + 1] = pack2bf(lz, lw);
        }
        __syncthreads();

        // prefetch next tile
        if (kt + 1 < ktot) {
            int kc = (kt + 1) * 32 + c4_l * 4;
            #pragma unroll
            for (int i = 0; i < 4; i++) {
                int row = row_l + i * 32;
                stA[i] = *reinterpret_cast<const float4*>(&A[(size_t)(bm + row) * K + kc]);
                stB[i] = *reinterpret_cast<const float4*>(&W[(size_t)(bn + row) * K + kc]);
            }
        }

        // compute 2 k16 steps
        #pragma unroll
        for (int ks = 0; ks < 2; ks++) {
            const int k2 = ks * 8 + tig;
            uint32_t ah[2][4], al[2][4];
            #pragma unroll
            for (int mt = 0; mt < 2; mt++) {
                int r = wm + mt * 16 + gid;
                ah[mt][0] = sAh[r][k2];     ah[mt][1] = sAh[r + 8][k2];
                ah[mt][2] = sAh[r][k2 + 4]; ah[mt][3] = sAh[r + 8][k2 + 4];
                al[mt][0] = sAl[r][k2];     al[mt][1] = sAl[r + 8][k2];
                al[mt][2] = sAl[r][k2 + 4]; al[mt][3] = sAl[r + 8][k2 + 4];
            }
            #pragma unroll
            for (int nt = 0; nt < 8; nt++) {
                int n = wn + nt * 8 + gid;
                uint32_t bh[2], bl[2];
                bh[0] = sBh[n][k2]; bh[1] = sBh[n][k2 + 4];
                bl[0] = sBl[n][k2]; bl[1] = sBl[n][k2 + 4];
                #pragma unroll
                for (int mt = 0; mt < 2; mt++) {
                    MMA_BF16(acc[mt][nt], ah[mt], bh);
                    MMA_BF16(acc[mt][nt], ah[mt], bl);
                    MMA_BF16(acc[mt][nt], al[mt], bh);
                }
            }
        }
    }

    // epilogue
    #pragma unroll
    for (int mt = 0; mt < 2; mt++) {
        int r0 = bm + wm + mt * 16 + gid;
        #pragma unroll
        for (int nt = 0; nt < 8; nt++) {
            int c = bn + wn + nt * 8 + tig * 2;
            float b0 = 0.f, b1 = 0.f;
            if (bias) { b0 = bias[c]; b1 = bias[c + 1]; }
            float v0 = acc[mt][nt][0] + b0, v1 = acc[mt][nt][1] + b1;
            float v2 = acc[mt][nt][2] + b0, v3 = acc[mt][nt][3] + b1;
            if (RES) {
                float2 ra = *reinterpret_cast<const float2*>(&res[(size_t)r0 * N + c]);
                float2 rb = *reinterpret_cast<const float2*>(&res[(size_t)(r0 + 8) * N + c]);
                v0 += ra.x; v1 += ra.y; v2 += rb.x; v3 += rb.y;
            }
            if (GELU) {
                v0 = 0.5f * v0 * (1.0f + erff(v0 * 0.70710678118654752f));
                v1 = 0.5f * v1 * (1.0f + erff(v1 * 0.70710678118654752f));
                v2 = 0.5f * v2 * (1.0f + erff(v2 * 0.70710678118654752f));
                v3 = 0.5f * v3 * (1.0f + erff(v3 * 0.70710678118654752f));
            }
            *reinterpret_cast<float2*>(&C[(size_t)r0 * N + c])       = make_float2(v0, v1);
            *reinterpret_cast<float2*>(&C[(size_t)(r0 + 8) * N + c]) = make_float2(v2, v3);
        }
    }
}

// ---------------- flash-style causal attention ----------------
// block = (q-tile of 16, h, b); 128 threads; K/V tiles of 32 in smem.
// thread: q = tid>>3, sub = tid&7. Scores: k = sub + i*8. PV: d = sub*4, 32+sub*4.
__global__ void __launch_bounds__(128)
attn_kernel(const float* __restrict__ Q, const float* __restrict__ Kp,
            const float* __restrict__ Vp, float* __restrict__ Y) {
    __shared__ float Qs[16 * 68];
    __shared__ float Ks[32 * 68];
    __shared__ float Vs[32 * 68];
    __shared__ float Ss[16 * 33];

    const int q0 = blockIdx.x * 16;
    const int h  = blockIdx.y;
    const int b  = blockIdx.z;
    const int tid = threadIdx.x;
    const int q = tid >> 3;
    const int sub = tid & 7;
    const size_t base = ((size_t)b * TT) * DD + h * HD;

    // load Q tile (16 x 64)
    #pragma unroll
    for (int i = 0; i < 2; i++) {
        int idx = tid + i * 128;
        int row = idx >> 4, c4 = idx & 15;
        *reinterpret_cast<float4*>(&Qs[row * 68 + c4 * 4]) =
            *reinterpret_cast<const float4*>(&Q[base + (size_t)(q0 + row) * DD + c4 * 4]);
    }

    float acc[8] = {0, 0, 0, 0, 0, 0, 0, 0};
    float m = -1e30f, l = 0.f;
    const int qg = q0 + q;
    const int ntiles = (q0 + 16 + 31) >> 5;

    for (int kt = 0; kt < ntiles; kt++) {
        int k0 = kt * 32;
        __syncthreads();
        #pragma unroll
        for (int i = 0; i < 4; i++) {
            int idx = tid + i * 128;
            int row = idx >> 4, c4 = idx & 15;
            *reinterpret_cast<float4*>(&Ks[row * 68 + c4 * 4]) =
                *reinterpret_cast<const float4*>(&Kp[base + (size_t)(k0 + row) * DD + c4 * 4]);
            *reinterpret_cast<float4*>(&Vs[row * 68 + c4 * 4]) =
                *reinterpret_cast<const float4*>(&Vp[base + (size_t)(k0 + row) * DD + c4 * 4]);
        }
        __syncthreads();

        // scores
        float s[4] = {0, 0, 0, 0};
        #pragma unroll
        for (int d4 = 0; d4 < 16; d4++) {
            float4 qq = *reinterpret_cast<const float4*>(&Qs[q * 68 + d4 * 4]);
            #pragma unroll
            for (int i = 0; i < 4; i++) {
                float4 kk = *reinterpret_cast<const float4*>(&Ks[(sub + i * 8) * 68 + d4 * 4]);
                s[i] += qq.x * kk.x + qq.y * kk.y + qq.z * kk.z + qq.w * kk.w;
            }
        }
        float mx = -1e30f;
        #pragma unroll
        for (int i = 0; i < 4; i++) {
            int kg = k0 + sub + i * 8;
            s[i] = (kg <= qg) ? s[i] * 0.125f : -1e30f;
            mx = fmaxf(mx, s[i]);
        }
        #pragma unroll
        for (int o = 1; o < 8; o <<= 1) mx = fmaxf(mx, __shfl_xor_sync(0xffffffffu, mx, o));
        float mnew = fmaxf(m, mx);
        float scale = __expf(m - mnew);
        float rs = 0.f;
        #pragma unroll
        for (int i = 0; i < 4; i++) {
            float p = __expf(s[i] - mnew);
            Ss[q * 33 + sub + i * 8] = p;
            rs += p;
        }
        #pragma unroll
        for (int o = 1; o < 8; o <<= 1) rs += __shfl_xor_sync(0xffffffffu, rs, o);
        l = l * scale + rs;
        m = mnew;
        #pragma unroll
        for (int j = 0; j < 8; j++) acc[j] *= scale;
        __syncwarp();

        // PV
        #pragma unroll 8
        for (int k = 0; k < 32; k++) {
            float p = Ss[q * 33 + k];
            float4 v0 = *reinterpret_cast<const float4*>(&Vs[k * 68 + sub * 4]);
            float4 v1 = *reinterpret_cast<const float4*>(&Vs[k * 68 + 32 + sub * 4]);
            acc[0] += p * v0.x; acc[1] += p * v0.y; acc[2] += p * v0.z; acc[3] += p * v0.w;
            acc[4] += p * v1.x; acc[5] += p * v1.y; acc[6] += p * v1.z; acc[7] += p * v1.w;
        }
        __syncwarp();
    }

    float inv = 1.0f / l;
    float4 o0 = make_float4(acc[0] * inv, acc[1] * inv, acc[2] * inv, acc[3] * inv);
    float4 o1 = make_float4(acc[4] * inv, acc[5] * inv, acc[6] * inv, acc[7] * inv);
    *reinterpret_cast<float4*>(&Y[base + (size_t)qg * DD + sub * 4]) = o0;
    *reinterpret_cast<float4*>(&Y[base + (size_t)qg * DD + 32 + sub * 4]) = o1;
}

// ---------------- launch ----------------
extern "C" void kernel_launch(void* const* d_in, const int* in_sizes, int n_in,
                              void* d_out, int out_size) {
    const int*   idx    = (const int*)  d_in[0];
    const float* tok    = (const float*)d_in[1];
    const float* pos    = (const float*)d_in[2];
    const float* ln1_w  = (const float*)d_in[3];
    const float* ln1_b  = (const float*)d_in[4];
    const float* Wq     = (const float*)d_in[5];
    const float* bq     = (const float*)d_in[6];
    const float* Wk     = (const float*)d_in[7];
    const float* bk     = (const float*)d_in[8];
    const float* Wv     = (const float*)d_in[9];
    const float* bv     = (const float*)d_in[10];
    const float* Wproj  = (const float*)d_in[11];
    const float* bproj  = (const float*)d_in[12];
    const float* ln2_w  = (const float*)d_in[13];
    const float* ln2_b  = (const float*)d_in[14];
    const float* W1     = (const float*)d_in[15];
    const float* b1     = (const float*)d_in[16];
    const float* W2     = (const float*)d_in[17];
    const float* b2     = (const float*)d_in[18];
    const float* lnf_w  = (const float*)d_in[19];
    const float* lnf_b  = (const float*)d_in[20];
    const float* Wlogit = (const float*)d_in[21];
    const float* Wdev   = (const float*)d_in[22];
    float* out = (float*)d_out;

    float *x, *h, *q, *k, *v, *y, *mid;
    cudaGetSymbolAddress((void**)&x,   g_x);
    cudaGetSymbolAddress((void**)&h,   g_h);
    cudaGetSymbolAddress((void**)&q,   g_q);
    cudaGetSymbolAddress((void**)&k,   g_k);
    cudaGetSymbolAddress((void**)&v,   g_v);
    cudaGetSymbolAddress((void**)&y,   g_y);
    cudaGetSymbolAddress((void**)&mid, g_mid);

    embed_kernel<<<BT, 256>>>(idx, tok, pos, x);

    dim3 gD(DD / 128, BT / 128);    // N=1024
    dim3 g4(D4 / 128, BT / 128);    // N=4096
    dim3 gV(VV / 128, BT / 128);
    dim3 ga(TT / 16, HH, BB);

    for (int l = 0; l < LL; l++) {
        const float* wq = Wq + (size_t)l * DD * DD;
        const float* wk = Wk + (size_t)l * DD * DD;
        const float* wv = Wv + (size_t)l * DD * DD;
        const float* wp = Wproj + (size_t)l * DD * DD;
        const float* w1 = W1 + (size_t)l * D4 * DD;
        const float* w2 = W2 + (size_t)l * DD * D4;

        ln_kernel<<<BT, 256>>>(x, h, ln1_w + l * DD, ln1_b + l * DD);

        mma_gemm<0, 0><<<gD, 256>>>(h, wq, bq + l * DD, nullptr, q, BT, DD, DD);
        mma_gemm<0, 0><<<gD, 256>>>(h, wk, bk + l * DD, nullptr, k, BT, DD, DD);
        mma_gemm<0, 0><<<gD, 256>>>(h, wv, bv + l * DD, nullptr, v, BT, DD, DD);

        attn_kernel<<<ga, 128>>>(q, k, v, y);

        mma_gemm<0, 1><<<gD, 256>>>(y, wp, bproj + l * DD, x, x, BT, DD, DD);

        ln_kernel<<<BT, 256>>>(x, h, ln2_w + l * DD, ln2_b + l * DD);

        mma_gemm<1, 0><<<g4, 256>>>(h, w1, b1 + (size_t)l * D4, nullptr, mid, BT, D4, DD);
        mma_gemm<0, 1><<<gD, 256>>>(mid, w2, b2 + l * DD, x, x, BT, DD, D4);
    }

    ln_kernel<<<BT, 256>>>(x, h, lnf_w, lnf_b);

    mma_gemm<0, 0><<<gV, 256>>>(h, Wlogit, nullptr, nullptr, out, BT, VV, DD);
    mma_gemm<0, 0><<<gV, 256>>>(h, Wdev, nullptr, nullptr, out + (size_t)BT * VV, BT, VV, DD);
}

// round 3
// speedup vs baseline: 4.0983x; 1.4799x over previous
#include <cuda_runtime.h>
#include <cuda_bf16.h>
#include <math.h>
#include <stdint.h>

// ---------------- problem constants ----------------
#define BB 4
#define TT 1024
#define DD 1024
#define HH 16
#define HD 64
#define LL 8
#define VV 4096
#define BT (BB*TT)       // 4096
#define D4 (4*DD)        // 4096

// ---------------- scratch (no alloc allowed) ----------------
__device__ float g_x[BT*DD];
__device__ float g_h[BT*DD];
__device__ float g_q[BT*DD];
__device__ float g_k[BT*DD];
__device__ float g_v[BT*DD];
__device__ float g_y[BT*DD];
__device__ float g_mid[(size_t)BT*D4];

// ---------------- helpers ----------------
__device__ __forceinline__ float warpSum(float v) {
    #pragma unroll
    for (int o = 16; o > 0; o >>= 1) v += __shfl_xor_sync(0xffffffffu, v, o);
    return v;
}

__device__ __forceinline__ uint32_t pack2bf(float a, float b) {
    __nv_bfloat162 h = __floats2bfloat162_rn(a, b);
    return *reinterpret_cast<uint32_t*>(&h);
}

__device__ __forceinline__ void split2(float f, float& hi, float& lo) {
    hi = __bfloat162float(__float2bfloat16_rn(f));
    lo = f - hi;
}

#define MMA_BF16(c, a, b0v, b1v) \
  asm volatile("mma.sync.aligned.m16n8k16.row.col.f32.bf16.bf16.f32 " \
    "{%0,%1,%2,%3}, {%4,%5,%6,%7}, {%8,%9}, {%0,%1,%2,%3};" \
    : "+f"((c)[0]), "+f"((c)[1]), "+f"((c)[2]), "+f"((c)[3]) \
    : "r"((a)[0]), "r"((a)[1]), "r"((a)[2]), "r"((a)[3]), "r"(b0v), "r"(b1v))

__device__ __forceinline__ void ldsm4(uint32_t* r, const uint32_t* p) {
    uint32_t a = (uint32_t)__cvta_generic_to_shared(p);
    asm volatile("ldmatrix.sync.aligned.m8n8.x4.shared.b16 {%0,%1,%2,%3}, [%4];"
        : "=r"(r[0]), "=r"(r[1]), "=r"(r[2]), "=r"(r[3]) : "r"(a));
}
__device__ __forceinline__ void ldsm4t(uint32_t* r, const uint32_t* p) {
    uint32_t a = (uint32_t)__cvta_generic_to_shared(p);
    asm volatile("ldmatrix.sync.aligned.m8n8.x4.trans.shared.b16 {%0,%1,%2,%3}, [%4];"
        : "=r"(r[0]), "=r"(r[1]), "=r"(r[2]), "=r"(r[3]) : "r"(a));
}

// ---------------- embedding ----------------
__global__ void embed_kernel(const int* __restrict__ idx,
                             const float* __restrict__ tok,
                             const float* __restrict__ pos,
                             float* __restrict__ x) {
    int row = blockIdx.x;
    int t   = row & (TT - 1);
    int token = idx[row];
    const float4* tr = reinterpret_cast<const float4*>(tok + (size_t)token * DD);
    const float4* pr = reinterpret_cast<const float4*>(pos + (size_t)t * DD);
    float4* xr = reinterpret_cast<float4*>(x + (size_t)row * DD);
    int i = threadIdx.x;
    float4 a = tr[i], p = pr[i];
    float4 o; o.x = a.x + p.x; o.y = a.y + p.y; o.z = a.z + p.z; o.w = a.w + p.w;
    xr[i] = o;
}

// ---------------- layernorm ----------------
__global__ void ln_kernel(const float* __restrict__ in, float* __restrict__ out,
                          const float* __restrict__ w, const float* __restrict__ b) {
    __shared__ float red[8];
    __shared__ float s_mean, s_rstd;
    int row = blockIdx.x;
    int tid = threadIdx.x;
    int lane = tid & 31, wid = tid >> 5;

    const float4* r = reinterpret_cast<const float4*>(in + (size_t)row * DD);
    float4 v = r[tid];

    float s = v.x + v.y + v.z + v.w;
    s = warpSum(s);
    if (lane == 0) red[wid] = s;
    __syncthreads();
    if (wid == 0) {
        float t = (lane < 8) ? red[lane] : 0.f;
        t = warpSum(t);
        if (lane == 0) s_mean = t * (1.0f / DD);
    }
    __syncthreads();
    float mean = s_mean;
    float dx = v.x - mean, dy = v.y - mean, dz = v.z - mean, dw = v.w - mean;
    float sq = dx*dx + dy*dy + dz*dz + dw*dw;
    sq = warpSum(sq);
    __syncthreads();
    if (lane == 0) red[wid] = sq;
    __syncthreads();
    if (wid == 0) {
        float t = (lane < 8) ? red[lane] : 0.f;
        t = warpSum(t);
        if (lane == 0) s_rstd = rsqrtf(t * (1.0f / DD) + 1e-5f);
    }
    __syncthreads();
    float rstd = s_rstd;

    const float4* wr = reinterpret_cast<const float4*>(w);
    const float4* br = reinterpret_cast<const float4*>(b);
    float4 ww = wr[tid], bb = br[tid];
    float4 o;
    o.x = dx * rstd * ww.x + bb.x;
    o.y = dy * rstd * ww.y + bb.y;
    o.z = dz * rstd * ww.z + bb.z;
    o.w = dw * rstd * ww.w + bb.w;
    reinterpret_cast<float4*>(out + (size_t)row * DD)[tid] = o;
}

// ---------------- bf16-split tensor-core GEMM, double buffered ----------------
// C[M,N] = A[M,K] * W[N,K]^T (+bias)(+res)(gelu)
// 128x128 tile, BK=32, 256 threads (8 warps 4x2), warp tile 32x64, ldmatrix.
// stage layout (u32): sAh[128][20] | sAl | sBh | sBl   (2560 each, 10240/stage)
__device__ __forceinline__ void stash_tile(uint32_t* st, const float4* stA, const float4* stB,
                                           int row_l, int c4_l) {
    #pragma unroll
    for (int i = 0; i < 4; i++) {
        int row = row_l + i * 32;
        float h0,l0,h1,l1,h2,l2,h3,l3;
        split2(stA[i].x,h0,l0); split2(stA[i].y,h1,l1);
        split2(stA[i].z,h2,l2); split2(stA[i].w,h3,l3);
        st[row*20 + c4_l*2]          = pack2bf(h0,h1);
        st[row*20 + c4_l*2 + 1]      = pack2bf(h2,h3);
        st[2560 + row*20 + c4_l*2]   = pack2bf(l0,l1);
        st[2560 + row*20 + c4_l*2+1] = pack2bf(l2,l3);
        split2(stB[i].x,h0,l0); split2(stB[i].y,h1,l1);
        split2(stB[i].z,h2,l2); split2(stB[i].w,h3,l3);
        st[5120 + row*20 + c4_l*2]   = pack2bf(h0,h1);
        st[5120 + row*20 + c4_l*2+1] = pack2bf(h2,h3);
        st[7680 + row*20 + c4_l*2]   = pack2bf(l0,l1);
        st[7680 + row*20 + c4_l*2+1] = pack2bf(l2,l3);
    }
}

template <int GELU, int RES>
__global__ void __launch_bounds__(256, 1)
mma_gemm(const float* __restrict__ A, const float* __restrict__ W,
         const float* __restrict__ bias, const float* __restrict__ res,
         float* __restrict__ C, int M, int N, int K) {
    extern __shared__ uint32_t sm[];

    const int t = threadIdx.x;
    const int lane = t & 31, wid = t >> 5;
    const int wm = (wid & 3) * 32;
    const int wn = (wid >> 2) * 64;
    const int gid = lane >> 2, tig = lane & 3;
    const int bm = blockIdx.y * 128;
    const int bn = blockIdx.x * 128;

    float acc[2][8][4];
    #pragma unroll
    for (int mt = 0; mt < 2; mt++)
        #pragma unroll
        for (int nt = 0; nt < 8; nt++)
            #pragma unroll
            for (int i = 0; i < 4; i++) acc[mt][nt][i] = 0.f;

    const int row_l = t >> 3;
    const int c4_l  = t & 7;

    // ldmatrix base offsets (within a stage)
    const int a_r = wm + (lane & 15);
    const int a_cofs = (lane >> 4) << 2;
    const int b_r = wn + (lane & 7) + ((lane & 16) ? 8 : 0);
    const int b_cofs = (lane & 8) ? 4 : 0;

    float4 stA[4], stB[4];
    #pragma unroll
    for (int i = 0; i < 4; i++) {
        int row = row_l + i * 32;
        stA[i] = *reinterpret_cast<const float4*>(&A[(size_t)(bm + row) * K + c4_l * 4]);
        stB[i] = *reinterpret_cast<const float4*>(&W[(size_t)(bn + row) * K + c4_l * 4]);
    }
    stash_tile(sm, stA, stB, row_l, c4_l);
    __syncthreads();

    const int ktot = K >> 5;
    for (int kt = 0; kt < ktot; kt++) {
        uint32_t* st = sm + (kt & 1) * 10240;
        // prefetch next tile (issue LDGs early, consume after MMAs)
        if (kt + 1 < ktot) {
            int kc = (kt + 1) * 32 + c4_l * 4;
            #pragma unroll
            for (int i = 0; i < 4; i++) {
                int row = row_l + i * 32;
                stA[i] = *reinterpret_cast<const float4*>(&A[(size_t)(bm + row) * K + kc]);
                stB[i] = *reinterpret_cast<const float4*>(&W[(size_t)(bn + row) * K + kc]);
            }
        }
        #pragma unroll
        for (int ks = 0; ks < 2; ks++) {
            uint32_t ah[2][4], al[2][4];
            int acol = ks * 8 + a_cofs;
            ldsm4(ah[0], st + (size_t)a_r * 20 + acol);
            ldsm4(ah[1], st + (size_t)(a_r + 16) * 20 + acol);
            ldsm4(al[0], st + 2560 + (size_t)a_r * 20 + acol);
            ldsm4(al[1], st + 2560 + (size_t)(a_r + 16) * 20 + acol);
            #pragma unroll
            for (int ntp = 0; ntp < 4; ntp++) {
                int brow = b_r + ntp * 16;
                int bcol = ks * 8 + b_cofs;
                uint32_t bh[4], bl[4];
                ldsm4(bh, st + 5120 + (size_t)brow * 20 + bcol);
                ldsm4(bl, st + 7680 + (size_t)brow * 20 + bcol);
                #pragma unroll
                for (int half = 0; half < 2; half++) {
                    int nt = ntp * 2 + half;
                    #pragma unroll
                    for (int mt = 0; mt < 2; mt++) {
                        MMA_BF16(acc[mt][nt], ah[mt], bh[half*2], bh[half*2+1]);
                        MMA_BF16(acc[mt][nt], ah[mt], bl[half*2], bl[half*2+1]);
                        MMA_BF16(acc[mt][nt], al[mt], bh[half*2], bh[half*2+1]);
                    }
                }
            }
        }
        if (kt + 1 < ktot)
            stash_tile(sm + ((kt + 1) & 1) * 10240, stA, stB, row_l, c4_l);
        __syncthreads();
    }

    // epilogue
    #pragma unroll
    for (int mt = 0; mt < 2; mt++) {
        int r0 = bm + wm + mt * 16 + gid;
        #pragma unroll
        for (int nt = 0; nt < 8; nt++) {
            int c = bn + wn + nt * 8 + tig * 2;
            float b0 = 0.f, b1 = 0.f;
            if (bias) { b0 = bias[c]; b1 = bias[c + 1]; }
            float v0 = acc[mt][nt][0] + b0, v1 = acc[mt][nt][1] + b1;
            float v2 = acc[mt][nt][2] + b0, v3 = acc[mt][nt][3] + b1;
            if (RES) {
                float2 ra = *reinterpret_cast<const float2*>(&res[(size_t)r0 * N + c]);
                float2 rb = *reinterpret_cast<const float2*>(&res[(size_t)(r0 + 8) * N + c]);
                v0 += ra.x; v1 += ra.y; v2 += rb.x; v3 += rb.y;
            }
            if (GELU) {
                v0 = 0.5f * v0 * (1.0f + erff(v0 * 0.70710678118654752f));
                v1 = 0.5f * v1 * (1.0f + erff(v1 * 0.70710678118654752f));
                v2 = 0.5f * v2 * (1.0f + erff(v2 * 0.70710678118654752f));
                v3 = 0.5f * v3 * (1.0f + erff(v3 * 0.70710678118654752f));
            }
            *reinterpret_cast<float2*>(&C[(size_t)r0 * N + c])       = make_float2(v0, v1);
            *reinterpret_cast<float2*>(&C[(size_t)(r0 + 8) * N + c]) = make_float2(v2, v3);
        }
    }
}

// ---------------- tensorized flash attention ----------------
// block: 64 q x (h,b), 128 threads (4 warps x 16q). K/V tiles of 32.
// scores: 3-term bf16-split MMA; softmax in registers; PV: 3-term MMA,
// P stays in registers (C-frag layout == A-frag layout), V via ldmatrix.trans.
// smem strides: 36 u32 per row (64 bf16 + pad).
__global__ void __launch_bounds__(128)
attn_kernel(const float* __restrict__ Q, const float* __restrict__ Kp,
            const float* __restrict__ Vp, float* __restrict__ Y) {
    __shared__ uint32_t Qh[64*36], Ql[64*36];
    __shared__ uint32_t Kh[32*36], Kl[32*36];
    __shared__ uint32_t Vh[32*36], Vl[32*36];

    const int q0 = blockIdx.x * 64;
    const int h  = blockIdx.y;
    const int b  = blockIdx.z;
    const int tid = threadIdx.x;
    const int lane = tid & 31, wid = tid >> 5;
    const int gid = lane >> 2, tig = lane & 3;
    const int wq = wid * 16;
    const size_t base = ((size_t)b * TT) * DD + h * HD;

    // stage Q (scaled by 1/sqrt(HD)=0.125), split hi/lo
    #pragma unroll
    for (int i = 0; i < 8; i++) {
        int idx = tid + i * 128;
        int row = idx >> 4, c4 = idx & 15;
        float4 qv = *reinterpret_cast<const float4*>(&Q[base + (size_t)(q0 + row) * DD + c4 * 4]);
        qv.x *= 0.125f; qv.y *= 0.125f; qv.z *= 0.125f; qv.w *= 0.125f;
        float h0,l0,h1,l1,h2,l2,h3,l3;
        split2(qv.x,h0,l0); split2(qv.y,h1,l1); split2(qv.z,h2,l2); split2(qv.w,h3,l3);
        Qh[row*36 + c4*2]   = pack2bf(h0,h1);
        Qh[row*36 + c4*2+1] = pack2bf(h2,h3);
        Ql[row*36 + c4*2]   = pack2bf(l0,l1);
        Ql[row*36 + c4*2+1] = pack2bf(l2,l3);
    }

    float m0 = -1e30f, m1 = -1e30f, l0s = 0.f, l1s = 0.f;
    float acc[8][4];
    #pragma unroll
    for (int i = 0; i < 8; i++)
        #pragma unroll
        for (int j = 0; j < 4; j++) acc[i][j] = 0.f;

    const int qg0 = q0 + wq + gid;
    const int qmax = q0 + wq + 15;
    const int ntiles = (q0 + 64) >> 5;

    // ldmatrix lane bases
    const int a_r = wq + (lane & 15);
    const int a_cofs = (lane >> 4) << 2;
    const int b_r = (lane & 7) + ((lane & 16) ? 8 : 0);
    const int b_cofs = (lane & 8) ? 4 : 0;
    const int v_r = (lane & 7) + ((lane & 8) ? 8 : 0);
    const int v_cofs = (lane & 16) ? 4 : 0;

    for (int kt = 0; kt < ntiles; kt++) {
        int k0 = kt * 32;
        __syncthreads();
        #pragma unroll
        for (int i = 0; i < 4; i++) {
            int idx = tid + i * 128;
            int row = idx >> 4, c4 = idx & 15;
            float4 kv = *reinterpret_cast<const float4*>(&Kp[base + (size_t)(k0 + row) * DD + c4 * 4]);
            float h0,l0,h1,l1,h2,l2,h3,l3;
            split2(kv.x,h0,l0); split2(kv.y,h1,l1); split2(kv.z,h2,l2); split2(kv.w,h3,l3);
            Kh[row*36 + c4*2]   = pack2bf(h0,h1);
            Kh[row*36 + c4*2+1] = pack2bf(h2,h3);
            Kl[row*36 + c4*2]   = pack2bf(l0,l1);
            Kl[row*36 + c4*2+1] = pack2bf(l2,l3);
            float4 vv = *reinterpret_cast<const float4*>(&Vp[base + (size_t)(k0 + row) * DD + c4 * 4]);
            split2(vv.x,h0,l0); split2(vv.y,h1,l1); split2(vv.z,h2,l2); split2(vv.w,h3,l3);
            Vh[row*36 + c4*2]   = pack2bf(h0,h1);
            Vh[row*36 + c4*2+1] = pack2bf(h2,h3);
            Vl[row*36 + c4*2]   = pack2bf(l0,l1);
            Vl[row*36 + c4*2+1] = pack2bf(l2,l3);
        }
        __syncthreads();
        if (k0 > qmax) continue;

        // ---- scores: S[16q x 32k] = Q . K^T (3-term split) ----
        float s[4][4];
        #pragma unroll
        for (int nt = 0; nt < 4; nt++)
            #pragma unroll
            for (int j = 0; j < 4; j++) s[nt][j] = 0.f;

        #pragma unroll
        for (int ks = 0; ks < 4; ks++) {
            uint32_t ah[4], al[4];
            int acol = ks * 8 + a_cofs;
            ldsm4(ah, Qh + (size_t)a_r * 36 + acol);
            ldsm4(al, Ql + (size_t)a_r * 36 + acol);
            #pragma unroll
            for (int ntp = 0; ntp < 2; ntp++) {
                int brow = b_r + ntp * 16;
                int bcol = ks * 8 + b_cofs;
                uint32_t bh[4], bl[4];
                ldsm4(bh, Kh + (size_t)brow * 36 + bcol);
                ldsm4(bl, Kl + (size_t)brow * 36 + bcol);
                #pragma unroll
                for (int half = 0; half < 2; half++) {
                    int nt = ntp * 2 + half;
                    MMA_BF16(s[nt], ah, bh[half*2], bh[half*2+1]);
                    MMA_BF16(s[nt], ah, bl[half*2], bl[half*2+1]);
                    MMA_BF16(s[nt], al, bh[half*2], bh[half*2+1]);
                }
            }
        }

        // causal mask
        if (k0 + 31 > q0 + wq) {
            #pragma unroll
            for (int nt = 0; nt < 4; nt++) {
                int kg = k0 + nt * 8 + tig * 2;
                if (kg     > qg0)     s[nt][0] = -1e30f;
                if (kg + 1 > qg0)     s[nt][1] = -1e30f;
                if (kg     > qg0 + 8) s[nt][2] = -1e30f;
                if (kg + 1 > qg0 + 8) s[nt][3] = -1e30f;
            }
        }

        // online softmax (rows gid and gid+8)
        float mx0 = -1e30f, mx1 = -1e30f;
        #pragma unroll
        for (int nt = 0; nt < 4; nt++) {
            mx0 = fmaxf(mx0, fmaxf(s[nt][0], s[nt][1]));
            mx1 = fmaxf(mx1, fmaxf(s[nt][2], s[nt][3]));
        }
        mx0 = fmaxf(mx0, __shfl_xor_sync(0xffffffffu, mx0, 1));
        mx0 = fmaxf(mx0, __shfl_xor_sync(0xffffffffu, mx0, 2));
        mx1 = fmaxf(mx1, __shfl_xor_sync(0xffffffffu, mx1, 1));
        mx1 = fmaxf(mx1, __shfl_xor_sync(0xffffffffu, mx1, 2));
        float mn0 = fmaxf(m0, mx0), mn1 = fmaxf(m1, mx1);
        float sc0 = __expf(m0 - mn0), sc1 = __expf(m1 - mn1);
        m0 = mn0; m1 = mn1;
        float rs0 = 0.f, rs1 = 0.f;
        #pragma unroll
        for (int nt = 0; nt < 4; nt++) {
            s[nt][0] = __expf(s[nt][0] - mn0);
            s[nt][1] = __expf(s[nt][1] - mn0);
            s[nt][2] = __expf(s[nt][2] - mn1);
            s[nt][3] = __expf(s[nt][3] - mn1);
            rs0 += s[nt][0] + s[nt][1];
            rs1 += s[nt][2] + s[nt][3];
        }
        rs0 += __shfl_xor_sync(0xffffffffu, rs0, 1);
        rs0 += __shfl_xor_sync(0xffffffffu, rs0, 2);
        rs1 += __shfl_xor_sync(0xffffffffu, rs1, 1);
        rs1 += __shfl_xor_sync(0xffffffffu, rs1, 2);
        l0s = l0s * sc0 + rs0;
        l1s = l1s * sc1 + rs1;
        #pragma unroll
        for (int ntd = 0; ntd < 8; ntd++) {
            acc[ntd][0] *= sc0; acc[ntd][1] *= sc0;
            acc[ntd][2] *= sc1; acc[ntd][3] *= sc1;
        }

        // ---- PV: acc += P . V (3-term split, P from registers) ----
        #pragma unroll
        for (int ks2 = 0; ks2 < 2; ks2++) {
            int e = ks2 * 2, o = e + 1;
            uint32_t ph[4], pl[4];
            {
                float h0,L0,h1,L1;
                split2(s[e][0],h0,L0); split2(s[e][1],h1,L1);
                ph[0] = pack2bf(h0,h1); pl[0] = pack2bf(L0,L1);
                split2(s[e][2],h0,L0); split2(s[e][3],h1,L1);
                ph[1] = pack2bf(h0,h1); pl[1] = pack2bf(L0,L1);
                split2(s[o][0],h0,L0); split2(s[o][1],h1,L1);
                ph[2] = pack2bf(h0,h1); pl[2] = pack2bf(L0,L1);
                split2(s[o][2],h0,L0); split2(s[o][3],h1,L1);
                ph[3] = pack2bf(h0,h1); pl[3] = pack2bf(L0,L1);
            }
            #pragma unroll
            for (int ntp = 0; ntp < 4; ntp++) {
                int vrow = ks2 * 16 + v_r;
                int vcol = ntp * 8 + v_cofs;
                uint32_t bh[4], bl[4];
                ldsm4t(bh, Vh + (size_t)vrow * 36 + vcol);
                ldsm4t(bl, Vl + (size_t)vrow * 36 + vcol);
                #pragma unroll
                for (int half = 0; half < 2; half++) {
                    int ntd = ntp * 2 + half;
                    MMA_BF16(acc[ntd], ph, bh[half*2], bh[half*2+1]);
                    MMA_BF16(acc[ntd], ph, bl[half*2], bl[half*2+1]);
                    MMA_BF16(acc[ntd], pl, bh[half*2], bh[half*2+1]);
                }
            }
        }
    }

    // write out
    float inv0 = 1.0f / l0s, inv1 = 1.0f / l1s;
    #pragma unroll
    for (int ntd = 0; ntd < 8; ntd++) {
        int d = ntd * 8 + tig * 2;
        *reinterpret_cast<float2*>(&Y[base + (size_t)qg0 * DD + d]) =
            make_float2(acc[ntd][0] * inv0, acc[ntd][1] * inv0);
        *reinterpret_cast<float2*>(&Y[base + (size_t)(qg0 + 8) * DD + d]) =
            make_float2(acc[ntd][2] * inv1, acc[ntd][3] * inv1);
    }
}

// ---------------- launch ----------------
extern "C" void kernel_launch(void* const* d_in, const int* in_sizes, int n_in,
                              void* d_out, int out_size) {
    const int*   idx    = (const int*)  d_in[0];
    const float* tok    = (const float*)d_in[1];
    const float* pos    = (const float*)d_in[2];
    const float* ln1_w  = (const float*)d_in[3];
    const float* ln1_b  = (const float*)d_in[4];
    const float* Wq     = (const float*)d_in[5];
    const float* bq     = (const float*)d_in[6];
    const float* Wk     = (const float*)d_in[7];
    const float* bk     = (const float*)d_in[8];
    const float* Wv     = (const float*)d_in[9];
    const float* bv     = (const float*)d_in[10];
    const float* Wproj  = (const float*)d_in[11];
    const float* bproj  = (const float*)d_in[12];
    const float* ln2_w  = (const float*)d_in[13];
    const float* ln2_b  = (const float*)d_in[14];
    const float* W1     = (const float*)d_in[15];
    const float* b1     = (const float*)d_in[16];
    const float* W2     = (const float*)d_in[17];
    const float* b2     = (const float*)d_in[18];
    const float* lnf_w  = (const float*)d_in[19];
    const float* lnf_b  = (const float*)d_in[20];
    const float* Wlogit = (const float*)d_in[21];
    const float* Wdev   = (const float*)d_in[22];
    float* out = (float*)d_out;

    float *x, *h, *q, *k, *v, *y, *mid;
    cudaGetSymbolAddress((void**)&x,   g_x);
    cudaGetSymbolAddress((void**)&h,   g_h);
    cudaGetSymbolAddress((void**)&q,   g_q);
    cudaGetSymbolAddress((void**)&k,   g_k);
    cudaGetSymbolAddress((void**)&v,   g_v);
    cudaGetSymbolAddress((void**)&y,   g_y);
    cudaGetSymbolAddress((void**)&mid, g_mid);

    const int SMEM = 81920;
    cudaFuncSetAttribute(mma_gemm<0,0>, cudaFuncAttributeMaxDynamicSharedMemorySize, SMEM);
    cudaFuncSetAttribute(mma_gemm<0,1>, cudaFuncAttributeMaxDynamicSharedMemorySize, SMEM);
    cudaFuncSetAttribute(mma_gemm<1,0>, cudaFuncAttributeMaxDynamicSharedMemorySize, SMEM);

    embed_kernel<<<BT, 256>>>(idx, tok, pos, x);

    dim3 gD(DD / 128, BT / 128);    // N=1024
    dim3 g4(D4 / 128, BT / 128);    // N=4096
    dim3 gV(VV / 128, BT / 128);
    dim3 ga(TT / 64, HH, BB);

    for (int l = 0; l < LL; l++) {
        const float* wq = Wq + (size_t)l * DD * DD;
        const float* wk = Wk + (size_t)l * DD * DD;
        const float* wv = Wv + (size_t)l * DD * DD;
        const float* wp = Wproj + (size_t)l * DD * DD;
        const float* w1 = W1 + (size_t)l * D4 * DD;
        const float* w2 = W2 + (size_t)l * DD * D4;

        ln_kernel<<<BT, 256>>>(x, h, ln1_w + l * DD, ln1_b + l * DD);

        mma_gemm<0, 0><<<gD, 256, SMEM>>>(h, wq, bq + l * DD, nullptr, q, BT, DD, DD);
        mma_gemm<0, 0><<<gD, 256, SMEM>>>(h, wk, bk + l * DD, nullptr, k, BT, DD, DD);
        mma_gemm<0, 0><<<gD, 256, SMEM>>>(h, wv, bv + l * DD, nullptr, v, BT, DD, DD);

        attn_kernel<<<ga, 128>>>(q, k, v, y);

        mma_gemm<0, 1><<<gD, 256, SMEM>>>(y, wp, bproj + l * DD, x, x, BT, DD, DD);

        ln_kernel<<<BT, 256>>>(x, h, ln2_w + l * DD, ln2_b + l * DD);

        mma_gemm<1, 0><<<g4, 256, SMEM>>>(h, w1, b1 + (size_t)l * D4, nullptr, mid, BT, D4, DD);
        mma_gemm<0, 1><<<gD, 256, SMEM>>>(mid, w2, b2 + l * DD, x, x, BT, DD, D4);
    }

    ln_kernel<<<BT, 256>>>(x, h, lnf_w, lnf_b);

    mma_gemm<0, 0><<<gV, 256, SMEM>>>(h, Wlogit, nullptr, nullptr, out, BT, VV, DD);
    mma_gemm<0, 0><<<gV, 256, SMEM>>>(h, Wdev, nullptr, nullptr, out + (size_t)BT * VV, BT, VV, DD);
}